// round 16
// baseline (speedup 1.0000x reference)
#include <cuda_runtime.h>
#include <cstdint>
#include <math_constants.h>

#define BB 128
#define NN 16384
#define KK 32
#define CAP 2048                       // per-row candidate cap (bench needs ~100)
#define THR 2.5f                       // fast-path threshold
#define NBINS 2048                     // fallback histogram (11-bit)
#define TPB_F 256
#define BPT (NBINS / TPB_F)            // 8 bins per thread (fallback scan)

// zero_collect shape (PROVEN ~39.8us): 4096 CTAs (32/row), 256 thr.
#define TPB_Z 256
#define ZSEG 512
#define ZGRID (BB * (NN / ZSEG))       // 4096
#define ZF4_PER_T (ZSEG * KK / 4 / TPB_Z)  // 16

// eps = FLT_EPSILON = 2^-23 ; eps^2 = 2^-46 ; 1/eps^2 = 2^46 (exact powers of 2)
#define EPSf    1.1920929e-07f
#define E2f     1.4210854715202004e-14f
#define INV_E2f 7.0368744177664e13f

// Device scratch (allocation-free rule: __device__ globals; zero-initialized).
// (val, idx-bits) interleaved -> one 64-bit load per candidate in finalize.
__device__ float2   g_cpair[BB * CAP];
__device__ unsigned g_cnt[BB];         // reset by finalize (sole reader) per launch

__device__ __forceinline__ unsigned key_of(float f) {
    unsigned u = __float_as_uint(f);
    return (u & 0x80000000u) ? ~u : (u | 0x80000000u);
}
__device__ __forceinline__ float key_to_float(unsigned k) {
    unsigned u = (k & 0x80000000u) ? (k & 0x7FFFFFFFu) : ~k;
    return __uint_as_float(u);
}

// ---------------------------------------------------------------------------
// zero_collect (byte-identical to the r15 kernel, ~39.8us): streaming
// zero-fill of the whole output (exact for all non-candidates, since
// s_j >= 1 -> relu(1-s_j) == 0) fused with the threshold collect of the
// matching 512 x's (x >= THR: provable superset of the exact top-32 and of
// every eps-window contributor, since ulp(THR) > eps).
// ---------------------------------------------------------------------------
__global__ void __launch_bounds__(TPB_Z) zero_collect_kernel(const float* __restrict__ x,
                                                             float4* __restrict__ out) {
    const int cid  = blockIdx.x;              // b*32 + seg
    const int b    = cid >> 5;
    const int n0   = (cid & 31) * ZSEG;
    const int tid  = threadIdx.x;
    const int lane = tid & 31;

    // Issue the x loads first (2 floats/thread, coalesced), hide under stores.
    const float2 xv = ((const float2*)(x + (size_t)b * NN + n0))[tid];

    // Zero the 64 KB output slab of this segment.
    const float4 z = make_float4(0.f, 0.f, 0.f, 0.f);
    float4* basep = out + ((size_t)b * NN + n0) * (KK / 4) + tid;
    #pragma unroll
    for (int k = 0; k < ZF4_PER_T; k++)
        __stcs(basep + k * TPB_Z, z);

    // Threshold collect: ballot-aggregated global atomic append.
    float vals[2] = {xv.x, xv.y};
    #pragma unroll
    for (int c = 0; c < 2; c++) {
        const bool pred = vals[c] >= THR;
        const unsigned bm = __ballot_sync(0xFFFFFFFFu, pred);
        if (bm) {
            const int leader = __ffs(bm) - 1;
            unsigned basec = 0;
            if (lane == leader) basec = atomicAdd(&g_cnt[b], (unsigned)__popc(bm));
            basec = __shfl_sync(0xFFFFFFFFu, basec, leader);
            if (pred) {
                const unsigned p = basec + (unsigned)__popc(bm & ((1u << lane) - 1u));
                if (p < CAP) {
                    const unsigned idx = (unsigned)(n0 + 2 * tid + c);
                    g_cpair[b * CAP + p] = make_float2(vals[c], __uint_as_float(idx));
                }
            }
        }
    }
}

// ---------------------------------------------------------------------------
// finalize v4: 128 CTAs (one per row) x 256 thr. Same structure as r15 (7.6us)
// with the LDS-latency-bound loops fixed: the candidate array is padded to a
// multiple of 32 with -INF (neutral for BOTH rank-select and c_j), letting the
// inner loops run with compile-time unroll bodies -> 8 independent LDS in
// flight instead of a 1-per-29-cycle serial chain.
// ---------------------------------------------------------------------------
__global__ void __launch_bounds__(TPB_F) finalize_kernel(const float* __restrict__ x,
                                                         float* __restrict__ out) {
    extern __shared__ unsigned char sraw[];
    float*    cand = (float*)sraw;                   // 8 KB (+pad)
    unsigned* cidx = (unsigned*)(sraw + (CAP + 32) * 4);  // 8 KB
    unsigned* hist = (unsigned*)(sraw + (CAP + 32) * 8);  // 8 KB (fallback only)
    __shared__ unsigned csum[TPB_F];
    __shared__ float st[KK], sc[KK];
    __shared__ float partial[8 * KK];
    __shared__ unsigned s_m;
    __shared__ int s_bin;

    const int b   = blockIdx.x;
    const int tid = threadIdx.x;

    // Overlapped cold loads: prefetch candidate pair + count (independent).
    const float2  pf   = g_cpair[b * CAP + tid];     // in-bounds: CAP >= TPB_F
    const unsigned cnt0 = g_cnt[b];
    cand[tid] = pf.x;
    cidx[tid] = __float_as_uint(pf.y);
    __syncthreads();                  // all reads of g_cnt/g_cpair complete
    if (tid == 0) g_cnt[b] = 0;       // reset for next graph replay (sole reader)

    unsigned cnt = cnt0;
    if (cnt >= KK && cnt <= CAP) {
        // Remaining candidates beyond the prefetched 256 (rare on bench).
        for (unsigned i = tid + TPB_F; i < cnt; i += TPB_F) {
            const float2 p2 = g_cpair[b * CAP + i];
            cand[i] = p2.x;
            cidx[i] = __float_as_uint(p2.y);
        }
    } else {
        // ---- Exact fallback: 11-bit histogram select over the full row ----
        const float* xrow = x + (size_t)b * NN;
        for (int i = tid; i < NBINS; i += TPB_F) hist[i] = 0;
        if (tid == 0) s_m = 0;
        __syncthreads();
        for (int i = tid; i < NN; i += TPB_F) {
            unsigned dg = key_of(xrow[i]) >> 21;
            unsigned peers = __match_any_sync(0xFFFFFFFFu, dg);
            if ((tid & 31) == __ffs(peers) - 1)
                atomicAdd(&hist[dg], (unsigned)__popc(peers));
        }
        __syncthreads();
        {
            unsigned s = 0;
            #pragma unroll
            for (int j = 0; j < BPT; j++) s += hist[tid * BPT + j];
            csum[tid] = s;
            __syncthreads();
            #pragma unroll
            for (int off = 1; off < TPB_F; off <<= 1) {
                unsigned t = (tid + off < TPB_F) ? csum[tid + off] : 0u;
                __syncthreads();
                csum[tid] += t;
                __syncthreads();
            }
        }
        {
            unsigned incl = csum[tid];
            unsigned excl = (tid < TPB_F - 1) ? csum[tid + 1] : 0u;
            if (incl >= KK && excl < KK) {
                unsigned cum = excl;
                #pragma unroll
                for (int j = BPT - 1; j >= 0; j--) {
                    cum += hist[tid * BPT + j];
                    if (cum >= KK) { s_bin = tid * BPT + j; break; }
                }
            }
        }
        __syncthreads();
        const float binlo   = key_to_float((unsigned)s_bin << 21);
        const unsigned thrk = key_of(binlo - 2.0f * EPSf);
        for (int i = tid; i < NN; i += TPB_F) {
            float v = xrow[i];
            if (key_of(v) >= thrk) {
                unsigned p = atomicAdd(&s_m, 1u);
                if (p < CAP) { cand[p] = v; cidx[p] = (unsigned)i; }
            }
        }
        __syncthreads();
        cnt = min(s_m, (unsigned)CAP);
    }

    const int m  = (int)cnt;
    const int mp = (m + 31) & ~31;        // padded length (<= CAP+32)

    // Pad [m, mp) with -INF: neutral for rank (key tiny) AND c_j (term = 0).
    for (int i = m + tid; i < mp; i += TPB_F) cand[i] = -CUDART_INF_F;
    __syncthreads();

    // ---- Rank-select top-32 (descending), 8 LDS in flight per step ----
    for (int i0 = tid; i0 < m; i0 += TPB_F) {
        const unsigned kv = key_of(cand[i0]);
        int rank = 0;
        for (int i = 0; i < mp; i += 8) {
            #pragma unroll
            for (int u = 0; u < 8; u++) {
                const unsigned kw = key_of(cand[i + u]);
                rank += (kw > kv) || (kw == kv && (i + u) < i0);
            }
        }
        if (rank < KK) st[rank] = cand[i0];
    }
    __syncthreads();

    // ---- c_j = 1 - x_m_sum_j, chunk-parallel + 4-way unrolled ----
    // thread = (chunk ck = tid>>5, j = tid&31); chunks stride 8, unroll 4.
    {
        const int j = tid & 31, ck = tid >> 5;
        const float tj = st[j];
        float a0 = 0.f, a1 = 0.f, a2 = 0.f, a3 = 0.f;
        for (int i = ck; i < mp; i += 32) {
            float d0 = cand[i]      - tj;
            float d1 = cand[i + 8]  - tj;
            float d2 = cand[i + 16] - tj;
            float d3 = cand[i + 24] - tj;
            a0 += fmaxf(__fmaf_rn(-d0, d0, E2f), 0.f) * INV_E2f;
            a1 += fmaxf(__fmaf_rn(-d1, d1, E2f), 0.f) * INV_E2f;
            a2 += fmaxf(__fmaf_rn(-d2, d2, E2f), 0.f) * INV_E2f;
            a3 += fmaxf(__fmaf_rn(-d3, d3, E2f), 0.f) * INV_E2f;
        }
        partial[tid] = (a0 + a1) + (a2 + a3);
    }
    __syncthreads();
    if (tid < KK) {
        float acc = 0.f;
        #pragma unroll
        for (int ck = 0; ck < 8; ck++) acc += partial[ck * KK + tid];
        sc[tid] = 1.0f - acc;             // exact on fast path: terms are 0 or 1
    }
    __syncthreads();

    // ---- Scatter: rewrite the 32-wide segment of each candidate position ----
    for (int w = tid; w < m * 8; w += TPB_F) {
        const int p = w >> 3, q = w & 7, j0 = q * 4;
        const float xvv    = cand[p];
        const unsigned idx = cidx[p];
        float d;
        float4 r;
        d = xvv - st[j0 + 0]; r.x = fmaxf(__fmaf_rn(fmaxf(__fmaf_rn(-d, d, E2f), 0.f), INV_E2f, sc[j0 + 0]), 0.f);
        d = xvv - st[j0 + 1]; r.y = fmaxf(__fmaf_rn(fmaxf(__fmaf_rn(-d, d, E2f), 0.f), INV_E2f, sc[j0 + 1]), 0.f);
        d = xvv - st[j0 + 2]; r.z = fmaxf(__fmaf_rn(fmaxf(__fmaf_rn(-d, d, E2f), 0.f), INV_E2f, sc[j0 + 2]), 0.f);
        d = xvv - st[j0 + 3]; r.w = fmaxf(__fmaf_rn(fmaxf(__fmaf_rn(-d, d, E2f), 0.f), INV_E2f, sc[j0 + 3]), 0.f);
        float4* dst = (float4*)(out + ((size_t)b * NN + idx) * KK);
        dst[q] = r;
    }
}

// ---------------------------------------------------------------------------
extern "C" void kernel_launch(void* const* d_in, const int* in_sizes, int n_in,
                              void* d_out, int out_size) {
    const float* x = (const float*)d_in[0];
    float* out = (float*)d_out;
    (void)in_sizes; (void)n_in; (void)out_size;   // shapes fixed: (128,16384), k=32

    const int smem_f = (CAP + 32) * 8 + NBINS * 4;  // ~24.3 KB (cand+pad | cidx | hist)
    cudaFuncSetAttribute(finalize_kernel,
                         cudaFuncAttributeMaxDynamicSharedMemorySize, smem_f);

    zero_collect_kernel<<<ZGRID, TPB_Z>>>(x, (float4*)out);
    finalize_kernel<<<BB, TPB_F, smem_f>>>(x, out);
}

// round 17
// speedup vs baseline: 1.0136x; 1.0136x over previous
#include <cuda_runtime.h>
#include <cstdint>
#include <math_constants.h>

#define BB 128
#define NN 16384
#define KK 32
#define CAP 2048                       // per-row candidate cap (bench needs ~100)
#define THR 2.5f                       // fast-path threshold
#define NBINS 2048                     // fallback histogram (11-bit)
#define TPB_F 256
#define BPT (NBINS / TPB_F)            // 8 bins per thread (fallback scan)

// zero_collect shape (PROVEN ~39.8us): 4096 CTAs (32/row), 256 thr.
#define TPB_Z 256
#define ZSEG 512
#define ZGRID (BB * (NN / ZSEG))       // 4096
#define ZF4_PER_T (ZSEG * KK / 4 / TPB_Z)  // 16

// eps = FLT_EPSILON = 2^-23 ; eps^2 = 2^-46 ; 1/eps^2 = 2^46 (exact powers of 2)
#define EPSf    1.1920929e-07f
#define E2f     1.4210854715202004e-14f
#define INV_E2f 7.0368744177664e13f

// Device scratch (allocation-free rule: __device__ globals; zero-initialized).
__device__ float2   g_cpair[BB * CAP]; // (val, idx-bits) interleaved
__device__ unsigned g_cnt[BB];         // reset by finalize (sole reader) per launch

__device__ __forceinline__ unsigned key_of(float f) {
    unsigned u = __float_as_uint(f);
    return (u & 0x80000000u) ? ~u : (u | 0x80000000u);
}
__device__ __forceinline__ float key_to_float(unsigned k) {
    unsigned u = (k & 0x80000000u) ? (k & 0x7FFFFFFFu) : ~k;
    return __uint_as_float(u);
}

// ---------------------------------------------------------------------------
// zero_collect (hot path identical to the proven ~39.8us kernel): streaming
// zero-fill of the whole output (exact for all non-candidates, since
// s_j >= 1 -> relu(1-s_j) == 0) fused with the threshold collect of the
// matching 512 x's (x >= THR: provable superset of the exact top-32 and of
// every eps-window contributor, since ulp(THR) > eps). Ends with a PDL
// trigger so the finalize kernel's launch ramp overlaps our store drain.
// ---------------------------------------------------------------------------
__global__ void __launch_bounds__(TPB_Z) zero_collect_kernel(const float* __restrict__ x,
                                                             float4* __restrict__ out) {
    const int cid  = blockIdx.x;              // b*32 + seg
    const int b    = cid >> 5;
    const int n0   = (cid & 31) * ZSEG;
    const int tid  = threadIdx.x;
    const int lane = tid & 31;

    // Issue the x loads first (2 floats/thread, coalesced), hide under stores.
    const float2 xv = ((const float2*)(x + (size_t)b * NN + n0))[tid];

    // Zero the 64 KB output slab of this segment.
    const float4 z = make_float4(0.f, 0.f, 0.f, 0.f);
    float4* basep = out + ((size_t)b * NN + n0) * (KK / 4) + tid;
    #pragma unroll
    for (int k = 0; k < ZF4_PER_T; k++)
        __stcs(basep + k * TPB_Z, z);

    // Threshold collect: ballot-aggregated global atomic append.
    float vals[2] = {xv.x, xv.y};
    #pragma unroll
    for (int c = 0; c < 2; c++) {
        const bool pred = vals[c] >= THR;
        const unsigned bm = __ballot_sync(0xFFFFFFFFu, pred);
        if (bm) {
            const int leader = __ffs(bm) - 1;
            unsigned basec = 0;
            if (lane == leader) basec = atomicAdd(&g_cnt[b], (unsigned)__popc(bm));
            basec = __shfl_sync(0xFFFFFFFFu, basec, leader);
            if (pred) {
                const unsigned p = basec + (unsigned)__popc(bm & ((1u << lane) - 1u));
                if (p < CAP) {
                    const unsigned idx = (unsigned)(n0 + 2 * tid + c);
                    g_cpair[b * CAP + p] = make_float2(vals[c], __uint_as_float(idx));
                }
            }
        }
    }

    // PDL: let the dependent finalize kernel begin launching now; memory
    // visibility is provided by its cudaGridDependencySynchronize().
    cudaTriggerProgrammaticLaunchCompletion();
}

// ---------------------------------------------------------------------------
// finalize (body = proven r15/r16 logic) with a PDL prologue: the CTA is
// resident and set up while zero_collect drains; cudaGridDependencySynchronize
// is the visibility join right before the first dependent load.
// ---------------------------------------------------------------------------
__global__ void __launch_bounds__(TPB_F) finalize_kernel(const float* __restrict__ x,
                                                         float* __restrict__ out) {
    extern __shared__ unsigned char sraw[];
    float*    cand = (float*)sraw;                        // 8 KB (+pad)
    unsigned* cidx = (unsigned*)(sraw + (CAP + 32) * 4);  // 8 KB
    unsigned* hist = (unsigned*)(sraw + (CAP + 32) * 8);  // 8 KB (fallback only)
    __shared__ unsigned csum[TPB_F];
    __shared__ float st[KK], sc[KK];
    __shared__ float partial[8 * KK];
    __shared__ unsigned s_m;
    __shared__ int s_bin;

    const int b   = blockIdx.x;
    const int tid = threadIdx.x;

    // ---- PDL join: primary's writes become visible after this ----
    cudaGridDependencySynchronize();

    // Overlapped cold loads: prefetch candidate pair + count (independent).
    const float2  pf    = g_cpair[b * CAP + tid];    // in-bounds: CAP >= TPB_F
    const unsigned cnt0 = g_cnt[b];
    cand[tid] = pf.x;
    cidx[tid] = __float_as_uint(pf.y);
    __syncthreads();                  // all reads of g_cnt/g_cpair complete
    if (tid == 0) g_cnt[b] = 0;       // reset for next graph replay (sole reader)

    unsigned cnt = cnt0;
    if (cnt >= KK && cnt <= CAP) {
        // Remaining candidates beyond the prefetched 256 (rare on bench).
        for (unsigned i = tid + TPB_F; i < cnt; i += TPB_F) {
            const float2 p2 = g_cpair[b * CAP + i];
            cand[i] = p2.x;
            cidx[i] = __float_as_uint(p2.y);
        }
    } else {
        // ---- Exact fallback: 11-bit histogram select over the full row ----
        const float* xrow = x + (size_t)b * NN;
        for (int i = tid; i < NBINS; i += TPB_F) hist[i] = 0;
        if (tid == 0) s_m = 0;
        __syncthreads();
        for (int i = tid; i < NN; i += TPB_F) {
            unsigned dg = key_of(xrow[i]) >> 21;
            unsigned peers = __match_any_sync(0xFFFFFFFFu, dg);
            if ((tid & 31) == __ffs(peers) - 1)
                atomicAdd(&hist[dg], (unsigned)__popc(peers));
        }
        __syncthreads();
        {
            unsigned s = 0;
            #pragma unroll
            for (int j = 0; j < BPT; j++) s += hist[tid * BPT + j];
            csum[tid] = s;
            __syncthreads();
            #pragma unroll
            for (int off = 1; off < TPB_F; off <<= 1) {
                unsigned t = (tid + off < TPB_F) ? csum[tid + off] : 0u;
                __syncthreads();
                csum[tid] += t;
                __syncthreads();
            }
        }
        {
            unsigned incl = csum[tid];
            unsigned excl = (tid < TPB_F - 1) ? csum[tid + 1] : 0u;
            if (incl >= KK && excl < KK) {
                unsigned cum = excl;
                #pragma unroll
                for (int j = BPT - 1; j >= 0; j--) {
                    cum += hist[tid * BPT + j];
                    if (cum >= KK) { s_bin = tid * BPT + j; break; }
                }
            }
        }
        __syncthreads();
        const float binlo   = key_to_float((unsigned)s_bin << 21);
        const unsigned thrk = key_of(binlo - 2.0f * EPSf);
        for (int i = tid; i < NN; i += TPB_F) {
            float v = xrow[i];
            if (key_of(v) >= thrk) {
                unsigned p = atomicAdd(&s_m, 1u);
                if (p < CAP) { cand[p] = v; cidx[p] = (unsigned)i; }
            }
        }
        __syncthreads();
        cnt = min(s_m, (unsigned)CAP);
    }

    const int m  = (int)cnt;
    const int mp = (m + 31) & ~31;        // padded length (<= CAP+32)

    // Pad [m, mp) with -INF: neutral for rank (key tiny) AND c_j (term = 0).
    for (int i = m + tid; i < mp; i += TPB_F) cand[i] = -CUDART_INF_F;
    __syncthreads();

    // ---- Rank-select top-32 (descending), 8 LDS in flight per step ----
    for (int i0 = tid; i0 < m; i0 += TPB_F) {
        const unsigned kv = key_of(cand[i0]);
        int rank = 0;
        for (int i = 0; i < mp; i += 8) {
            #pragma unroll
            for (int u = 0; u < 8; u++) {
                const unsigned kw = key_of(cand[i + u]);
                rank += (kw > kv) || (kw == kv && (i + u) < i0);
            }
        }
        if (rank < KK) st[rank] = cand[i0];
    }
    __syncthreads();

    // ---- c_j = 1 - x_m_sum_j, chunk-parallel + 4-way unrolled ----
    {
        const int j = tid & 31, ck = tid >> 5;
        const float tj = st[j];
        float a0 = 0.f, a1 = 0.f, a2 = 0.f, a3 = 0.f;
        for (int i = ck; i < mp; i += 32) {
            float d0 = cand[i]      - tj;
            float d1 = cand[i + 8]  - tj;
            float d2 = cand[i + 16] - tj;
            float d3 = cand[i + 24] - tj;
            a0 += fmaxf(__fmaf_rn(-d0, d0, E2f), 0.f) * INV_E2f;
            a1 += fmaxf(__fmaf_rn(-d1, d1, E2f), 0.f) * INV_E2f;
            a2 += fmaxf(__fmaf_rn(-d2, d2, E2f), 0.f) * INV_E2f;
            a3 += fmaxf(__fmaf_rn(-d3, d3, E2f), 0.f) * INV_E2f;
        }
        partial[tid] = (a0 + a1) + (a2 + a3);
    }
    __syncthreads();
    if (tid < KK) {
        float acc = 0.f;
        #pragma unroll
        for (int ck = 0; ck < 8; ck++) acc += partial[ck * KK + tid];
        sc[tid] = 1.0f - acc;             // exact on fast path: terms are 0 or 1
    }
    __syncthreads();

    // ---- Scatter: rewrite the 32-wide segment of each candidate position ----
    for (int w = tid; w < m * 8; w += TPB_F) {
        const int p = w >> 3, q = w & 7, j0 = q * 4;
        const float xvv    = cand[p];
        const unsigned idx = cidx[p];
        float d;
        float4 r;
        d = xvv - st[j0 + 0]; r.x = fmaxf(__fmaf_rn(fmaxf(__fmaf_rn(-d, d, E2f), 0.f), INV_E2f, sc[j0 + 0]), 0.f);
        d = xvv - st[j0 + 1]; r.y = fmaxf(__fmaf_rn(fmaxf(__fmaf_rn(-d, d, E2f), 0.f), INV_E2f, sc[j0 + 1]), 0.f);
        d = xvv - st[j0 + 2]; r.z = fmaxf(__fmaf_rn(fmaxf(__fmaf_rn(-d, d, E2f), 0.f), INV_E2f, sc[j0 + 2]), 0.f);
        d = xvv - st[j0 + 3]; r.w = fmaxf(__fmaf_rn(fmaxf(__fmaf_rn(-d, d, E2f), 0.f), INV_E2f, sc[j0 + 3]), 0.f);
        float4* dst = (float4*)(out + ((size_t)b * NN + idx) * KK);
        dst[q] = r;
    }
}

// ---------------------------------------------------------------------------
extern "C" void kernel_launch(void* const* d_in, const int* in_sizes, int n_in,
                              void* d_out, int out_size) {
    const float* x = (const float*)d_in[0];
    float* out = (float*)d_out;
    (void)in_sizes; (void)n_in; (void)out_size;   // shapes fixed: (128,16384), k=32

    const int smem_f = (CAP + 32) * 8 + NBINS * 4;  // ~24.3 KB (cand+pad | cidx | hist)
    cudaFuncSetAttribute(finalize_kernel,
                         cudaFuncAttributeMaxDynamicSharedMemorySize, smem_f);

    zero_collect_kernel<<<ZGRID, TPB_Z>>>(x, (float4*)out);

    // PDL launch: finalize's ramp overlaps zero_collect's store drain.
    cudaLaunchConfig_t cfg = {};
    cfg.gridDim  = dim3(BB, 1, 1);
    cfg.blockDim = dim3(TPB_F, 1, 1);
    cfg.dynamicSmemBytes = smem_f;
    cfg.stream = 0;
    cudaLaunchAttribute attrs[1];
    attrs[0].id = cudaLaunchAttributeProgrammaticStreamSerialization;
    attrs[0].val.programmaticStreamSerializationAllowed = 1;
    cfg.attrs = attrs;
    cfg.numAttrs = 1;
    cudaLaunchKernelEx(&cfg, finalize_kernel, x, out);
}